// round 4
// baseline (speedup 1.0000x reference)
#include <cuda_runtime.h>

// Fixed-index per-tile partials keep the reduction deterministic no matter
// which block steals which tile.
__device__ double g_tile_partial[20480];
__device__ double g_seg_partial[256];
__device__ int    g_ticket = 0;       // reset by last block each call
__device__ int    g_done_count = 0;   // reset by last block each call

#define TILE_F4  4096     // float4 per tile = 64 KB
#define NT       512      // threads per block
#define LN2_D    0.69314718055994530942

__global__ void __launch_bounds__(NT, 4)
fused_kernel(const float* __restrict__ pred, long long n, long long n4,
             int n_tiles,
             const float* __restrict__ action_probs,
             const float* __restrict__ value,
             const float* __restrict__ critic_value,
             const int*   __restrict__ segments,
             int B, int totalBlocks,
             float* __restrict__ out, double inv_BL) {
    __shared__ float sh_ws[2][16];
    __shared__ int   sh_tile[2];
    __shared__ bool  sh_is_last;

    const int t    = threadIdx.x;
    const int lane = t & 31;
    const int wid  = t >> 5;
    const float4* __restrict__ p4 = reinterpret_cast<const float4*>(pred);

    // ---------------- segment rows (blocks 0..B-1 do one row first) --------
    if (blockIdx.x < (unsigned)B) {
        __shared__ float sh_logp[512];
        __shared__ short sh_segid[512];
        __shared__ float sh_segsum[513];
        __shared__ int   sh_nseg;

        const int L = 512;
        const int row = blockIdx.x;
        const long long base = (long long)row * L;

        sh_logp[t] = __logf(action_probs[base + t]);
        __syncthreads();

        if (t == 0) {
            float acc = 0.0f;
            int cnt = 0;
            for (int l = 0; l < L; l++) {
                sh_segid[l] = (short)cnt;
                acc += sh_logp[l];
                if (segments[base + l] != 0) {
                    sh_segsum[cnt] = acc;
                    acc = 0.0f;
                    cnt++;
                }
            }
            sh_segsum[cnt] = acc;   // trailing tail segment
            sh_nseg = cnt;
        }
        __syncthreads();

        float slp = sh_segsum[sh_segid[t]];
        // Faithful reference quirk: tail of the LAST batch row stays zero.
        if (row == B - 1 && (int)sh_segid[t] == sh_nseg) slp = 0.0f;

        float adv  = value[base + t] - critic_value[base + t];
        float term = -adv * slp + 0.5f * adv * adv;

        #pragma unroll
        for (int o = 16; o > 0; o >>= 1)
            term += __shfl_down_sync(0xffffffffu, term, o);
        if (lane == 0) sh_ws[0][wid] = term;
        __syncthreads();
        if (t == 0) {
            double blk = 0.0;
            #pragma unroll
            for (int i = 0; i < 16; i++) blk += (double)sh_ws[0][i];
            g_seg_partial[row] = blk;
        }
        __syncthreads();
    }

    // ---------------- work-stealing plogp tiles ----------------------------
    // One ticket prefetched ahead (double-buffered) so ATOMG latency is hidden.
    if (t == 0) sh_tile[0] = atomicAdd(&g_ticket, 1);
    __syncthreads();
    int cur = sh_tile[0];
    int buf = 1, par = 0;

    while (cur < n_tiles) {
        if (t == 0) sh_tile[buf] = atomicAdd(&g_ticket, 1);

        const float4* __restrict__ bp = p4 + (long long)cur * TILE_F4 + t;

        // First half of tile: 4 independent streaming LDG.128 (MLP_p1 = 4).
        float4 a = __ldcs(bp);
        float4 b = __ldcs(bp + 512);
        float4 c = __ldcs(bp + 1024);
        float4 d = __ldcs(bp + 1536);

        float s0, s1, s2, s3;
        s0 = a.x * __log2f(a.x);
        s0 = fmaf(a.y, __log2f(a.y), s0);
        s0 = fmaf(a.z, __log2f(a.z), s0);
        s0 = fmaf(a.w, __log2f(a.w), s0);
        s1 = b.x * __log2f(b.x);
        s1 = fmaf(b.y, __log2f(b.y), s1);
        s1 = fmaf(b.z, __log2f(b.z), s1);
        s1 = fmaf(b.w, __log2f(b.w), s1);
        s2 = c.x * __log2f(c.x);
        s2 = fmaf(c.y, __log2f(c.y), s2);
        s2 = fmaf(c.z, __log2f(c.z), s2);
        s2 = fmaf(c.w, __log2f(c.w), s2);
        s3 = d.x * __log2f(d.x);
        s3 = fmaf(d.y, __log2f(d.y), s3);
        s3 = fmaf(d.z, __log2f(d.z), s3);
        s3 = fmaf(d.w, __log2f(d.w), s3);

        // Second half.
        a = __ldcs(bp + 2048);
        b = __ldcs(bp + 2560);
        c = __ldcs(bp + 3072);
        d = __ldcs(bp + 3584);

        s0 = fmaf(a.x, __log2f(a.x), s0);
        s0 = fmaf(a.y, __log2f(a.y), s0);
        s0 = fmaf(a.z, __log2f(a.z), s0);
        s0 = fmaf(a.w, __log2f(a.w), s0);
        s1 = fmaf(b.x, __log2f(b.x), s1);
        s1 = fmaf(b.y, __log2f(b.y), s1);
        s1 = fmaf(b.z, __log2f(b.z), s1);
        s1 = fmaf(b.w, __log2f(b.w), s1);
        s2 = fmaf(c.x, __log2f(c.x), s2);
        s2 = fmaf(c.y, __log2f(c.y), s2);
        s2 = fmaf(c.z, __log2f(c.z), s2);
        s2 = fmaf(c.w, __log2f(c.w), s2);
        s3 = fmaf(d.x, __log2f(d.x), s3);
        s3 = fmaf(d.y, __log2f(d.y), s3);
        s3 = fmaf(d.z, __log2f(d.z), s3);
        s3 = fmaf(d.w, __log2f(d.w), s3);

        float s = (s0 + s1) + (s2 + s3);   // log2 domain; ln2 folded at the end

        #pragma unroll
        for (int o = 16; o > 0; o >>= 1)
            s += __shfl_down_sync(0xffffffffu, s, o);
        if (lane == 0) sh_ws[par][wid] = s;
        __syncthreads();   // publishes sh_ws[par] AND sh_tile[buf]
        if (t == 0) {
            double blk = 0.0;
            #pragma unroll
            for (int i = 0; i < 16; i++) blk += (double)sh_ws[par][i];
            g_tile_partial[cur] = blk;
        }
        cur = sh_tile[buf];
        buf ^= 1;
        par ^= 1;
    }

    // ---------------- last-block finalize -----------------------------------
    if (t == 0) {
        __threadfence();
        int prev = atomicAdd(&g_done_count, 1);
        sh_is_last = (prev == totalBlocks - 1);
    }
    __syncthreads();
    if (!sh_is_last) return;

    __shared__ double sh_d[32];

    // Scalar tail beyond the full tiles (deterministic: fixed thread mapping).
    const long long tail_start = (long long)n_tiles * TILE_F4 * 4;
    float ts = 0.0f;
    for (long long i = tail_start + t; i < n; i += NT) {
        float v = pred[i];
        ts = fmaf(v, __log2f(v), ts);
    }

    double e = (double)ts;
    for (int i = t; i < n_tiles; i += NT) e += g_tile_partial[i];
    double v = e * (0.005 * LN2_D);
    for (int i = t; i < B; i += NT) v += g_seg_partial[i];

    #pragma unroll
    for (int o = 16; o > 0; o >>= 1)
        v += __shfl_down_sync(0xffffffffu, v, o);
    if (lane == 0) sh_d[wid] = v;
    __syncthreads();
    if (t == 0) {
        double tot = 0.0;
        #pragma unroll
        for (int i = 0; i < 16; i++) tot += sh_d[i];
        out[0] = (float)(tot * inv_BL);
        g_ticket = 0;        // reset for next (graph-replayed) call
        g_done_count = 0;
    }
}

extern "C" void kernel_launch(void* const* d_in, const int* in_sizes, int n_in,
                              void* d_out, int out_size) {
    const float* pred         = (const float*)d_in[0];
    const float* action_probs = (const float*)d_in[1];
    const float* value        = (const float*)d_in[2];
    const float* critic_value = (const float*)d_in[3];
    const int*   segments     = (const int*)d_in[4];

    const long long n_pred = in_sizes[0];   // B*L*V
    const int BL = in_sizes[1];             // B*L
    const int B = BL / 512;

    float* out = (float*)d_out;

    const long long n4 = n_pred >> 2;
    int n_tiles = (int)(n4 / TILE_F4);      // full tiles; tail in finalize
    if (n_tiles > 20480) n_tiles = 20480;   // partial-array bound (ample here)

    // Exactly one wave: 148 SMs x 4 blocks of 512 threads.
    const int totalBlocks = 592;

    fused_kernel<<<totalBlocks, NT>>>(pred, n_pred, n4, n_tiles,
                                      action_probs, value, critic_value,
                                      segments, B, totalBlocks,
                                      out, 1.0 / (double)BL);
}